// round 1
// baseline (speedup 1.0000x reference)
#include <cuda_runtime.h>

#define NN   50000
#define EE   800000
#define FDIM 256
#define HDIM 256
#define LDIM 128
#define BN_EPS 1e-5f

// ---------------- scratch (static device globals; no allocation) ----------------
__device__ float g_deg [NN];
__device__ float g_dinv[NN];
__device__ float g_bufA[(size_t)NN * HDIM];   // 51.2 MB
__device__ float g_bufB[(size_t)NN * HDIM];   // 51.2 MB
__device__ float g_stats[2 * HDIM];           // [0:256) sum, [256:512) sumsq
__device__ float g_ss   [2 * HDIM];           // [0:256) scale, [256:512) shift

// ---------------- helpers ----------------
__device__ __forceinline__ void red_add_v4(float* addr, float4 v) {
    // vectorized global reduction (sm_90+): 16B atomic add, no return
    asm volatile("red.global.add.v4.f32 [%0], {%1, %2, %3, %4};"
                 :: "l"(addr), "f"(v.x), "f"(v.y), "f"(v.z), "f"(v.w)
                 : "memory");
}

// ---------------- degree / normalization ----------------
__global__ void k_deg_init() {
    int i = blockIdx.x * blockDim.x + threadIdx.x;
    if (i < NN) g_deg[i] = 1.0f;   // self-loop
}

__global__ void k_deg_count(const int* __restrict__ dst) {
    int e = blockIdx.x * blockDim.x + threadIdx.x;
    if (e < EE) atomicAdd(&g_deg[dst[e]], 1.0f);
}

__global__ void k_dinv() {
    int i = blockIdx.x * blockDim.x + threadIdx.x;
    if (i < NN) g_dinv[i] = rsqrtf(g_deg[i]);
}

// ---------------- SGEMM: C[M,ncols] = A[M,256] @ W[256,ncols] (+bias) ----------
// BM=128, BN=64, BK=16, 256 threads, 8x4 micro-tile per thread.
__global__ void sgemm256(const float* __restrict__ A, const float* __restrict__ W,
                         const float* __restrict__ bias, float* __restrict__ C,
                         int M, int ncols) {
    __shared__ float As[16][128];
    __shared__ float Bs[16][64];

    int tid = threadIdx.x;
    int tx  = tid & 15;        // 0..15 -> 4 cols each
    int ty  = tid >> 4;        // 0..15 -> 8 rows each
    int rowBase = blockIdx.x * 128;
    int colBase = blockIdx.y * 64;

    float acc[8][4];
#pragma unroll
    for (int i = 0; i < 8; i++)
#pragma unroll
        for (int j = 0; j < 4; j++) acc[i][j] = 0.0f;

    for (int k0 = 0; k0 < 256; k0 += 16) {
        // A tile: 128x16 = 512 float4, 2 per thread
#pragma unroll
        for (int i = 0; i < 2; i++) {
            int f4 = tid + i * 256;          // 0..511
            int r  = f4 >> 2;                // 0..127
            int ks = (f4 & 3) << 2;          // 0,4,8,12
            float4 v = make_float4(0.f, 0.f, 0.f, 0.f);
            int gr = rowBase + r;
            if (gr < M) v = *(const float4*)&A[(size_t)gr * 256 + k0 + ks];
            As[ks + 0][r] = v.x; As[ks + 1][r] = v.y;
            As[ks + 2][r] = v.z; As[ks + 3][r] = v.w;
        }
        // B tile: 16x64 = 256 float4, 1 per thread
        {
            int k = tid >> 4;                // 0..15
            int c = (tid & 15) << 2;         // 0..60
            float4 v = *(const float4*)&W[(size_t)(k0 + k) * ncols + colBase + c];
            *(float4*)&Bs[k][c] = v;
        }
        __syncthreads();

#pragma unroll
        for (int kk = 0; kk < 16; kk++) {
            float4 a0 = *(float4*)&As[kk][ty * 8];
            float4 a1 = *(float4*)&As[kk][ty * 8 + 4];
            float4 b4 = *(float4*)&Bs[kk][tx * 4];
            float a[8] = {a0.x, a0.y, a0.z, a0.w, a1.x, a1.y, a1.z, a1.w};
            float b[4] = {b4.x, b4.y, b4.z, b4.w};
#pragma unroll
            for (int i = 0; i < 8; i++)
#pragma unroll
                for (int j = 0; j < 4; j++)
                    acc[i][j] = fmaf(a[i], b[j], acc[i][j]);
        }
        __syncthreads();
    }

#pragma unroll
    for (int i = 0; i < 8; i++) {
        int gr = rowBase + ty * 8 + i;
        if (gr < M) {
            int gc = colBase + tx * 4;
            float4 o = make_float4(acc[i][0], acc[i][1], acc[i][2], acc[i][3]);
            if (bias) {
                o.x += bias[gc]; o.y += bias[gc + 1];
                o.z += bias[gc + 2]; o.w += bias[gc + 3];
            }
            *(float4*)&C[(size_t)gr * ncols + gc] = o;
        }
    }
}

// ---------------- aggregation ----------------
// out = h * dinv[i]^2 (self-loop) + bias   (elementwise init before edge atomics)
__global__ void k_agg_init(const float* __restrict__ h, float* __restrict__ out,
                           const float* __restrict__ bias) {
    size_t i4 = (size_t)blockIdx.x * blockDim.x + threadIdx.x;      // float4 index
    if (i4 >= (size_t)NN * HDIM / 4) return;
    size_t base = i4 * 4;
    int n = (int)(base >> 8);          // /256
    int f = (int)(base & 255);
    float c = g_dinv[n]; c = c * c;
    float4 v = *(const float4*)&h[base];
    float4 b = *(const float4*)&bias[f];
    v.x = v.x * c + b.x; v.y = v.y * c + b.y;
    v.z = v.z * c + b.z; v.w = v.w * c + b.w;
    *(float4*)&out[base] = v;
}

// one edge per 64-thread group (4 edges / 256-thread block); float4 gather + red.v4
__global__ void k_agg_edges(const int* __restrict__ src, const int* __restrict__ dst,
                            const float* __restrict__ h, float* __restrict__ out) {
    int slot = threadIdx.x >> 6;                 // 0..3
    int lane = threadIdx.x & 63;                 // 0..63
    int e = blockIdx.x * 4 + slot;
    if (e >= EE) return;
    int s = src[e], d = dst[e];
    float c = g_dinv[s] * g_dinv[d];
    float4 v = *(const float4*)&h[(size_t)s * 256 + lane * 4];
    v.x *= c; v.y *= c; v.z *= c; v.w *= c;
    red_add_v4(&out[(size_t)d * 256 + lane * 4], v);
}

// ---------------- batchnorm ----------------
__global__ void k_zero_stats() {
    int i = threadIdx.x;
    if (i < 2 * HDIM) g_stats[i] = 0.0f;
}

// each block: 256 rows x all 256 columns; thread = column
__global__ void k_bn_stats(const float* __restrict__ h) {
    int f = threadIdx.x;
    int r0 = blockIdx.x * 256;
    float s = 0.0f, sq = 0.0f;
    for (int r = r0; r < r0 + 256; r++) {
        if (r < NN) {
            float v = h[(size_t)r * 256 + f];
            s += v; sq += v * v;
        }
    }
    atomicAdd(&g_stats[f], s);
    atomicAdd(&g_stats[HDIM + f], sq);
}

__global__ void k_bn_final(const float* __restrict__ gamma, const float* __restrict__ beta) {
    int f = threadIdx.x;
    float inv_n = 1.0f / (float)NN;
    float m  = g_stats[f] * inv_n;
    float v  = g_stats[HDIM + f] * inv_n - m * m;
    float sc = gamma[f] * rsqrtf(v + BN_EPS);
    g_ss[f]        = sc;
    g_ss[HDIM + f] = beta[f] - m * sc;
}

// h = relu(h*scale + shift), in place
__global__ void k_bn_relu(float* __restrict__ h) {
    size_t i4 = (size_t)blockIdx.x * blockDim.x + threadIdx.x;
    if (i4 >= (size_t)NN * HDIM / 4) return;
    size_t base = i4 * 4;
    int f = (int)(base & 255);
    float4 v  = *(float4*)&h[base];
    float4 sc = *(const float4*)&g_ss[f];
    float4 sh = *(const float4*)&g_ss[HDIM + f];
    v.x = fmaxf(v.x * sc.x + sh.x, 0.0f);
    v.y = fmaxf(v.y * sc.y + sh.y, 0.0f);
    v.z = fmaxf(v.z * sc.z + sh.z, 0.0f);
    v.w = fmaxf(v.w * sc.w + sh.w, 0.0f);
    *(float4*)&h[base] = v;
}

// ---------------- launch ----------------
extern "C" void kernel_launch(void* const* d_in, const int* in_sizes, int n_in,
                              void* d_out, int out_size) {
    const float* x   = (const float*)d_in[0];
    const int*   ei  = (const int*)  d_in[1];   // [2, E]: src then dst
    const float* W0  = (const float*)d_in[2];
    const float* b0  = (const float*)d_in[3];
    const float* g0  = (const float*)d_in[4];
    const float* be0 = (const float*)d_in[5];
    const float* W1  = (const float*)d_in[6];
    const float* b1  = (const float*)d_in[7];
    const float* g1  = (const float*)d_in[8];
    const float* be1 = (const float*)d_in[9];
    const float* Wmu = (const float*)d_in[10];
    const float* bmu = (const float*)d_in[11];
    const float* Wlv = (const float*)d_in[12];
    const float* blv = (const float*)d_in[13];
    float* out = (float*)d_out;

    const int* src = ei;
    const int* dst = ei + EE;

    float *bufA = nullptr, *bufB = nullptr;
    cudaGetSymbolAddress((void**)&bufA, g_bufA);
    cudaGetSymbolAddress((void**)&bufB, g_bufB);

    const int NB_N   = (NN + 255) / 256;                 // 196
    const int NB_E   = (EE + 255) / 256;                 // 3125
    const int NB_E4  = (EE + 3) / 4;                     // 200000
    const int NB_EL  = (int)(((size_t)NN * HDIM / 4 + 255) / 256);  // 12500
    const dim3 G_GEMM_H((NN + 127) / 128, HDIM / 64);    // (391, 4)
    const dim3 G_GEMM_L((NN + 127) / 128, LDIM / 64);    // (391, 2)

    // --- degree / dinv (shared by both layers) ---
    k_deg_init <<<NB_N, 256>>>();
    k_deg_count<<<NB_E, 256>>>(dst);
    k_dinv     <<<NB_N, 256>>>();

    // --- layer 0 ---
    sgemm256   <<<G_GEMM_H, 256>>>(x, W0, nullptr, bufB, NN, HDIM);
    k_agg_init <<<NB_EL, 256>>>(bufB, bufA, b0);
    k_agg_edges<<<NB_E4, 256>>>(src, dst, bufB, bufA);
    k_zero_stats<<<1, 512>>>();
    k_bn_stats <<<NB_N, 256>>>(bufA);
    k_bn_final <<<1, 256>>>(g0, be0);
    k_bn_relu  <<<NB_EL, 256>>>(bufA);

    // --- layer 1 ---
    sgemm256   <<<G_GEMM_H, 256>>>(bufA, W1, nullptr, bufB, NN, HDIM);
    k_agg_init <<<NB_EL, 256>>>(bufB, bufA, b1);
    k_agg_edges<<<NB_E4, 256>>>(src, dst, bufB, bufA);
    k_zero_stats<<<1, 512>>>();
    k_bn_stats <<<NB_N, 256>>>(bufA);
    k_bn_final <<<1, 256>>>(g1, be1);
    k_bn_relu  <<<NB_EL, 256>>>(bufA);

    // --- heads: mu then logvar, flattened ---
    sgemm256<<<G_GEMM_L, 256>>>(bufA, Wmu, bmu, out,                    NN, LDIM);
    sgemm256<<<G_GEMM_L, 256>>>(bufA, Wlv, blv, out + (size_t)NN * LDIM, NN, LDIM);
}

// round 2
// speedup vs baseline: 1.7084x; 1.7084x over previous
#include <cuda_runtime.h>
#include <stdint.h>

#define NN   50000
#define EE   800000
#define HDIM 256
#define LDIM 128
#define BN_EPS 1e-5f

// ---------------- scratch (static device globals; no allocation) ----------------
__device__ float g_dinv[NN];
__device__ int   g_cnt [NN];        // edge in-degree (without self loop)
__device__ int   g_ptr [NN];        // CSR row start
__device__ int   g_pos [NN];        // fill cursor
__device__ int   g_csr_src [EE];
__device__ float g_csr_coef[EE];
__device__ float g_bufA[(size_t)NN * HDIM];   // 51.2 MB
__device__ float g_bufB[(size_t)NN * HDIM];   // 51.2 MB
__device__ float g_stats[2 * HDIM];           // sum / sumsq
__device__ float g_ss   [2 * HDIM];           // scale / shift

// ---------------- helpers ----------------
__device__ __forceinline__ uint32_t f2tf(float x) {
    uint32_t r;
    asm("cvt.rna.tf32.f32 %0, %1;" : "=r"(r) : "f"(x));
    return r;
}

__device__ __forceinline__ void mma_tf32(float* c, const uint32_t* a,
                                         uint32_t b0, uint32_t b1) {
    asm volatile(
        "mma.sync.aligned.m16n8k8.row.col.f32.tf32.tf32.f32 "
        "{%0,%1,%2,%3}, {%4,%5,%6,%7}, {%8,%9}, {%0,%1,%2,%3};\n"
        : "+f"(c[0]), "+f"(c[1]), "+f"(c[2]), "+f"(c[3])
        : "r"(a[0]), "r"(a[1]), "r"(a[2]), "r"(a[3]), "r"(b0), "r"(b1));
}

// ---------------- graph preprocessing ----------------
__global__ void k_cnt_zero() {
    int i = blockIdx.x * blockDim.x + threadIdx.x;
    if (i < NN) g_cnt[i] = 0;
}

__global__ void k_cnt(const int* __restrict__ dst) {
    int e = blockIdx.x * blockDim.x + threadIdx.x;
    if (e < EE) atomicAdd(&g_cnt[dst[e]], 1);
}

__global__ void k_dinv() {
    int i = blockIdx.x * blockDim.x + threadIdx.x;
    if (i < NN) g_dinv[i] = rsqrtf((float)g_cnt[i] + 1.0f);
}

// single-block exclusive scan over g_cnt -> g_ptr (and g_pos copy)
__global__ void k_scan() {
    __shared__ int sm[1024];
    int t = threadIdx.x;
    const int CH = (NN + 1023) / 1024;          // 49
    int lo = t * CH;
    int hi = lo + CH; if (hi > NN) hi = NN;
    int s = 0;
    for (int i = lo; i < hi; i++) s += g_cnt[i];
    sm[t] = s;
    __syncthreads();
    for (int off = 1; off < 1024; off <<= 1) {
        int v = (t >= off) ? sm[t - off] : 0;
        __syncthreads();
        sm[t] += v;
        __syncthreads();
    }
    int base = (t == 0) ? 0 : sm[t - 1];
    for (int i = lo; i < hi; i++) {
        g_ptr[i] = base;
        g_pos[i] = base;
        base += g_cnt[i];
    }
}

__global__ void k_fill(const int* __restrict__ src, const int* __restrict__ dst) {
    int e = blockIdx.x * blockDim.x + threadIdx.x;
    if (e >= EE) return;
    int s = src[e], d = dst[e];
    int p = atomicAdd(&g_pos[d], 1);
    g_csr_src[p]  = s;
    g_csr_coef[p] = g_dinv[s] * g_dinv[d];
}

// ---------------- tf32 tensor-core GEMM ----------------
// C[M, ncols] = A[M,256] @ W[256, ncols] (+bias). BM=128, BN=128, BK=32,
// 256 threads = 8 warps (4x2), warp tile 32x64, mma m16n8k8 tf32.
__global__ void sgemm_tf32(const float* __restrict__ A, const float* __restrict__ W,
                           const float* __restrict__ bias, float* __restrict__ C,
                           int M, int ncols) {
    __shared__ uint32_t As[32][132];   // [k][m]
    __shared__ uint32_t Bs[32][132];   // [k][n]

    int tid  = threadIdx.x;
    int wid  = tid >> 5;
    int lane = tid & 31;
    int g    = lane >> 2;      // groupID 0..7
    int tg   = lane & 3;       // thread-in-group 0..3
    int mb   = (wid & 3) * 32;     // warp m-offset in block
    int nb   = (wid >> 2) * 64;    // warp n-offset in block
    int rowBase = blockIdx.x * 128;
    int colBase = blockIdx.y * 128;

    float acc[2][8][4] = {};

    for (int k0 = 0; k0 < 256; k0 += 32) {
        // A tile 128x32: 4 float4 per thread, coalesced rows along k
#pragma unroll
        for (int i = 0; i < 4; i++) {
            int idx = tid + i * 256;
            int r   = idx >> 3;
            int c4  = (idx & 7) << 2;
            float4 v = make_float4(0.f, 0.f, 0.f, 0.f);
            int gr = rowBase + r;
            if (gr < M) v = *(const float4*)&A[(size_t)gr * 256 + k0 + c4];
            As[c4 + 0][r] = f2tf(v.x);
            As[c4 + 1][r] = f2tf(v.y);
            As[c4 + 2][r] = f2tf(v.z);
            As[c4 + 3][r] = f2tf(v.w);
        }
        // B tile 32x128: 4 float4 per thread, coalesced along n
#pragma unroll
        for (int i = 0; i < 4; i++) {
            int idx = tid + i * 256;
            int k   = idx >> 5;
            int n4  = (idx & 31) << 2;
            float4 v = *(const float4*)&W[(size_t)(k0 + k) * ncols + colBase + n4];
            Bs[k][n4 + 0] = f2tf(v.x);
            Bs[k][n4 + 1] = f2tf(v.y);
            Bs[k][n4 + 2] = f2tf(v.z);
            Bs[k][n4 + 3] = f2tf(v.w);
        }
        __syncthreads();

#pragma unroll
        for (int ks = 0; ks < 4; ks++) {
            int kk = ks * 8;
            uint32_t a[2][4];
#pragma unroll
            for (int im = 0; im < 2; im++) {
                int m0 = mb + im * 16;
                a[im][0] = As[kk + tg    ][m0 + g    ];
                a[im][1] = As[kk + tg    ][m0 + g + 8];
                a[im][2] = As[kk + tg + 4][m0 + g    ];
                a[im][3] = As[kk + tg + 4][m0 + g + 8];
            }
#pragma unroll
            for (int nt = 0; nt < 8; nt++) {
                uint32_t b0 = Bs[kk + tg    ][nb + nt * 8 + g];
                uint32_t b1 = Bs[kk + tg + 4][nb + nt * 8 + g];
                mma_tf32(acc[0][nt], a[0], b0, b1);
                mma_tf32(acc[1][nt], a[1], b0, b1);
            }
        }
        __syncthreads();
    }

    // epilogue
#pragma unroll
    for (int im = 0; im < 2; im++) {
#pragma unroll
        for (int nt = 0; nt < 8; nt++) {
            int row0 = rowBase + mb + im * 16 + g;
            int col  = colBase + nb + nt * 8 + tg * 2;
            float bx = 0.f, by = 0.f;
            if (bias) { bx = bias[col]; by = bias[col + 1]; }
            if (row0 < M) {
                float2 o = make_float2(acc[im][nt][0] + bx, acc[im][nt][1] + by);
                *(float2*)&C[(size_t)row0 * ncols + col] = o;
            }
            if (row0 + 8 < M) {
                float2 o = make_float2(acc[im][nt][2] + bx, acc[im][nt][3] + by);
                *(float2*)&C[(size_t)(row0 + 8) * ncols + col] = o;
            }
        }
    }
}

// ---------------- CSR aggregation (gather + accumulate, one write per row) -----
// 64 threads per node (float4 over 256 feats), 4 nodes per 256-thread block.
// out[n] = dinv[n]^2 * h[n] + bias + sum_j coef_j * h[src_j]
__global__ void k_agg_csr(const float* __restrict__ h, float* __restrict__ out,
                          const float* __restrict__ bias) {
    int node = blockIdx.x * 4 + (threadIdx.x >> 6);
    int lane = threadIdx.x & 63;
    if (node >= NN) return;
    int f = lane * 4;

    float di = g_dinv[node];
    float cs = di * di;
    float4 acc = *(const float4*)&h[(size_t)node * 256 + f];
    float4 b   = *(const float4*)&bias[f];
    acc.x = acc.x * cs + b.x;
    acc.y = acc.y * cs + b.y;
    acc.z = acc.z * cs + b.z;
    acc.w = acc.w * cs + b.w;

    int beg = g_ptr[node];
    int end = beg + g_cnt[node];
    if (beg < end) {
        int   s = g_csr_src[beg];
        float c = g_csr_coef[beg];
        for (int j = beg; j < end; j++) {
            float4 v = *(const float4*)&h[(size_t)s * 256 + f];
            int jn = j + 1;
            int   s2 = 0; float c2 = 0.f;
            if (jn < end) { s2 = g_csr_src[jn]; c2 = g_csr_coef[jn]; }
            acc.x += c * v.x; acc.y += c * v.y;
            acc.z += c * v.z; acc.w += c * v.w;
            s = s2; c = c2;
        }
    }
    *(float4*)&out[(size_t)node * 256 + f] = acc;
}

// ---------------- batchnorm ----------------
__global__ void k_zero_stats() {
    int i = threadIdx.x;
    if (i < 2 * HDIM) g_stats[i] = 0.0f;
}

__global__ void k_bn_stats(const float* __restrict__ h) {
    int f  = threadIdx.x;
    int r0 = blockIdx.x * 256;
    float s = 0.0f, sq = 0.0f;
    for (int r = r0; r < r0 + 256; r++) {
        if (r < NN) {
            float v = h[(size_t)r * 256 + f];
            s += v; sq += v * v;
        }
    }
    atomicAdd(&g_stats[f], s);
    atomicAdd(&g_stats[HDIM + f], sq);
}

__global__ void k_bn_final(const float* __restrict__ gamma, const float* __restrict__ beta) {
    int f = threadIdx.x;
    float inv_n = 1.0f / (float)NN;
    float m  = g_stats[f] * inv_n;
    float v  = g_stats[HDIM + f] * inv_n - m * m;
    float sc = gamma[f] * rsqrtf(v + BN_EPS);
    g_ss[f]        = sc;
    g_ss[HDIM + f] = beta[f] - m * sc;
}

__global__ void k_bn_relu(float* __restrict__ h) {
    size_t i4 = (size_t)blockIdx.x * blockDim.x + threadIdx.x;
    if (i4 >= (size_t)NN * HDIM / 4) return;
    size_t base = i4 * 4;
    int f = (int)(base & 255);
    float4 v  = *(float4*)&h[base];
    float4 sc = *(const float4*)&g_ss[f];
    float4 sh = *(const float4*)&g_ss[HDIM + f];
    v.x = fmaxf(v.x * sc.x + sh.x, 0.0f);
    v.y = fmaxf(v.y * sc.y + sh.y, 0.0f);
    v.z = fmaxf(v.z * sc.z + sh.z, 0.0f);
    v.w = fmaxf(v.w * sc.w + sh.w, 0.0f);
    *(float4*)&h[base] = v;
}

// ---------------- launch ----------------
extern "C" void kernel_launch(void* const* d_in, const int* in_sizes, int n_in,
                              void* d_out, int out_size) {
    const float* x   = (const float*)d_in[0];
    const int*   ei  = (const int*)  d_in[1];   // [2, E]: src then dst
    const float* W0  = (const float*)d_in[2];
    const float* b0  = (const float*)d_in[3];
    const float* g0  = (const float*)d_in[4];
    const float* be0 = (const float*)d_in[5];
    const float* W1  = (const float*)d_in[6];
    const float* b1  = (const float*)d_in[7];
    const float* g1  = (const float*)d_in[8];
    const float* be1 = (const float*)d_in[9];
    const float* Wmu = (const float*)d_in[10];
    const float* bmu = (const float*)d_in[11];
    const float* Wlv = (const float*)d_in[12];
    const float* blv = (const float*)d_in[13];
    float* out = (float*)d_out;

    const int* src = ei;
    const int* dst = ei + EE;

    float *bufA = nullptr, *bufB = nullptr;
    cudaGetSymbolAddress((void**)&bufA, g_bufA);
    cudaGetSymbolAddress((void**)&bufB, g_bufB);

    const int NB_N  = (NN + 255) / 256;
    const int NB_E  = (EE + 255) / 256;
    const int NB_AG = (NN + 3) / 4;                                   // 12500
    const int NB_EL = (int)(((size_t)NN * HDIM / 4 + 255) / 256);     // 12500
    const dim3 G_GEMM_H((NN + 127) / 128, 2);    // ncols=256
    const dim3 G_GEMM_L((NN + 127) / 128, 1);    // ncols=128

    // --- graph preprocessing (shared by both layers) ---
    k_cnt_zero<<<NB_N, 256>>>();
    k_cnt     <<<NB_E, 256>>>(dst);
    k_dinv    <<<NB_N, 256>>>();
    k_scan    <<<1, 1024>>>();
    k_fill    <<<NB_E, 256>>>(src, dst);

    // --- layer 0 ---
    sgemm_tf32 <<<G_GEMM_H, 256>>>(x, W0, nullptr, bufB, NN, HDIM);
    k_agg_csr  <<<NB_AG, 256>>>(bufB, bufA, b0);
    k_zero_stats<<<1, 512>>>();
    k_bn_stats <<<NB_N, 256>>>(bufA);
    k_bn_final <<<1, 256>>>(g0, be0);
    k_bn_relu  <<<NB_EL, 256>>>(bufA);

    // --- layer 1 ---
    sgemm_tf32 <<<G_GEMM_H, 256>>>(bufA, W1, nullptr, bufB, NN, HDIM);
    k_agg_csr  <<<NB_AG, 256>>>(bufB, bufA, b1);
    k_zero_stats<<<1, 512>>>();
    k_bn_stats <<<NB_N, 256>>>(bufA);
    k_bn_final <<<1, 256>>>(g1, be1);
    k_bn_relu  <<<NB_EL, 256>>>(bufA);

    // --- heads: mu then logvar, flattened ---
    sgemm_tf32<<<G_GEMM_L, 256>>>(bufA, Wmu, bmu, out,                     NN, LDIM);
    sgemm_tf32<<<G_GEMM_L, 256>>>(bufA, Wlv, blv, out + (size_t)NN * LDIM, NN, LDIM);
}

// round 3
// speedup vs baseline: 1.8119x; 1.0606x over previous
#include <cuda_runtime.h>
#include <cuda_fp16.h>
#include <stdint.h>

#define NN   50000
#define EE   800000
#define HDIM 256
#define LDIM 128
#define BN_EPS 1e-5f
#define SCAN_B 196          // ceil(NN/256)

// ---------------- scratch (static device globals; no allocation) ----------------
__device__ float  g_dinv[NN];
__device__ int    g_cnt [NN];
__device__ int    g_ptr [NN];
__device__ int    g_pos [NN];
__device__ int    g_bsum[256];
__device__ int    g_boff[256];
__device__ int    g_csr_src [EE];
__device__ float  g_csr_coef[EE];
__device__ __half g_h16[(size_t)NN * HDIM];      // 25.6 MB (GEMM out, agg in)
__device__ float  g_bufA[(size_t)NN * HDIM];     // 51.2 MB (agg out layer 0)
__device__ float  g_bufB[(size_t)NN * HDIM];     // 51.2 MB (agg out layer 1)
__device__ float  g_stats[2 * HDIM];             // col sum / sumsq
__device__ float  g_ss   [2 * HDIM];             // scale / shift

// ---------------- helpers ----------------
__device__ __forceinline__ uint32_t f2tf(float x) {
    uint32_t r;
    asm("cvt.rna.tf32.f32 %0, %1;" : "=r"(r) : "f"(x));
    return r;
}

__device__ __forceinline__ void mma_tf32(float* c, const uint32_t* a,
                                         uint32_t b0, uint32_t b1) {
    asm volatile(
        "mma.sync.aligned.m16n8k8.row.col.f32.tf32.tf32.f32 "
        "{%0,%1,%2,%3}, {%4,%5,%6,%7}, {%8,%9}, {%0,%1,%2,%3};\n"
        : "+f"(c[0]), "+f"(c[1]), "+f"(c[2]), "+f"(c[3])
        : "r"(a[0]), "r"(a[1]), "r"(a[2]), "r"(a[3]), "r"(b0), "r"(b1));
}

// ---------------- graph preprocessing ----------------
__global__ void k_cnt_zero() {
    int i = blockIdx.x * blockDim.x + threadIdx.x;
    if (i < NN) g_cnt[i] = 0;
}

__global__ void k_cnt(const int* __restrict__ dst) {
    int e = blockIdx.x * blockDim.x + threadIdx.x;
    if (e < EE) atomicAdd(&g_cnt[dst[e]], 1);
}

__global__ void k_dinv() {
    int i = blockIdx.x * blockDim.x + threadIdx.x;
    if (i < NN) g_dinv[i] = rsqrtf((float)g_cnt[i] + 1.0f);
    if (blockIdx.x == 0 && threadIdx.x < 2 * HDIM) g_stats[threadIdx.x] = 0.0f;
}

// per-block sums of g_cnt
__global__ void k_bsum() {
    __shared__ int sm[256];
    int t = threadIdx.x;
    int i = blockIdx.x * 256 + t;
    sm[t] = (i < NN) ? g_cnt[i] : 0;
    __syncthreads();
    for (int off = 128; off > 0; off >>= 1) {
        if (t < off) sm[t] += sm[t + off];
        __syncthreads();
    }
    if (t == 0) g_bsum[blockIdx.x] = sm[0];
}

// 1-block exclusive scan of 196 block sums
__global__ void k_bscan() {
    __shared__ int sm[256];
    int t = threadIdx.x;
    int v = (t < SCAN_B) ? g_bsum[t] : 0;
    sm[t] = v;
    __syncthreads();
    for (int off = 1; off < 256; off <<= 1) {
        int u = (t >= off) ? sm[t - off] : 0;
        __syncthreads();
        sm[t] += u;
        __syncthreads();
    }
    g_boff[t] = sm[t] - v;   // exclusive
}

// per-block local exclusive scan + block offset -> g_ptr / g_pos
__global__ void k_ptr() {
    __shared__ int sm[256];
    int t = threadIdx.x;
    int i = blockIdx.x * 256 + t;
    int c = (i < NN) ? g_cnt[i] : 0;
    sm[t] = c;
    __syncthreads();
    for (int off = 1; off < 256; off <<= 1) {
        int u = (t >= off) ? sm[t - off] : 0;
        __syncthreads();
        sm[t] += u;
        __syncthreads();
    }
    if (i < NN) {
        int p = g_boff[blockIdx.x] + sm[t] - c;
        g_ptr[i] = p;
        g_pos[i] = p;
    }
}

__global__ void k_fill(const int* __restrict__ src, const int* __restrict__ dst) {
    int e = blockIdx.x * blockDim.x + threadIdx.x;
    if (e >= EE) return;
    int s = src[e], d = dst[e];
    int p = atomicAdd(&g_pos[d], 1);
    g_csr_src[p]  = s;
    g_csr_coef[p] = g_dinv[s] * g_dinv[d];
}

// ---------------- tf32 tensor-core GEMM ----------------
// C[M, ncols] = act(A)[M,256] @ W[256, ncols] (+bias)
// FUSE_BN: act(v) = relu(v * g_ss[f] + g_ss[256+f]) applied at A-tile load.
// OUT16:   write fp16 output (hidden layers) instead of fp32.
template <bool FUSE_BN, bool OUT16>
__global__ void sgemm_tf32(const float* __restrict__ A, const float* __restrict__ W,
                           const float* __restrict__ bias, void* __restrict__ Cv,
                           int M, int ncols) {
    __shared__ uint32_t As[32][132];   // [k][m]
    __shared__ uint32_t Bs[32][132];   // [k][n]

    int tid  = threadIdx.x;
    int wid  = tid >> 5;
    int lane = tid & 31;
    int g    = lane >> 2;
    int tg   = lane & 3;
    int mb   = (wid & 3) * 32;
    int nb   = (wid >> 2) * 64;
    int rowBase = blockIdx.x * 128;
    int colBase = blockIdx.y * 128;

    float acc[2][8][4] = {};

    for (int k0 = 0; k0 < 256; k0 += 32) {
#pragma unroll
        for (int i = 0; i < 4; i++) {
            int idx = tid + i * 256;
            int r   = idx >> 3;
            int c4  = (idx & 7) << 2;
            float4 v = make_float4(0.f, 0.f, 0.f, 0.f);
            int gr = rowBase + r;
            if (gr < M) v = *(const float4*)&A[(size_t)gr * 256 + k0 + c4];
            if (FUSE_BN) {
                float4 sc = *(const float4*)&g_ss[k0 + c4];
                float4 sh = *(const float4*)&g_ss[256 + k0 + c4];
                v.x = fmaxf(v.x * sc.x + sh.x, 0.0f);
                v.y = fmaxf(v.y * sc.y + sh.y, 0.0f);
                v.z = fmaxf(v.z * sc.z + sh.z, 0.0f);
                v.w = fmaxf(v.w * sc.w + sh.w, 0.0f);
            }
            As[c4 + 0][r] = f2tf(v.x);
            As[c4 + 1][r] = f2tf(v.y);
            As[c4 + 2][r] = f2tf(v.z);
            As[c4 + 3][r] = f2tf(v.w);
        }
#pragma unroll
        for (int i = 0; i < 4; i++) {
            int idx = tid + i * 256;
            int k   = idx >> 5;
            int n4  = (idx & 31) << 2;
            float4 v = *(const float4*)&W[(size_t)(k0 + k) * ncols + colBase + n4];
            Bs[k][n4 + 0] = f2tf(v.x);
            Bs[k][n4 + 1] = f2tf(v.y);
            Bs[k][n4 + 2] = f2tf(v.z);
            Bs[k][n4 + 3] = f2tf(v.w);
        }
        __syncthreads();

#pragma unroll
        for (int ks = 0; ks < 4; ks++) {
            int kk = ks * 8;
            uint32_t a[2][4];
#pragma unroll
            for (int im = 0; im < 2; im++) {
                int m0 = mb + im * 16;
                a[im][0] = As[kk + tg    ][m0 + g    ];
                a[im][1] = As[kk + tg    ][m0 + g + 8];
                a[im][2] = As[kk + tg + 4][m0 + g    ];
                a[im][3] = As[kk + tg + 4][m0 + g + 8];
            }
#pragma unroll
            for (int nt = 0; nt < 8; nt++) {
                uint32_t b0 = Bs[kk + tg    ][nb + nt * 8 + g];
                uint32_t b1 = Bs[kk + tg + 4][nb + nt * 8 + g];
                mma_tf32(acc[0][nt], a[0], b0, b1);
                mma_tf32(acc[1][nt], a[1], b0, b1);
            }
        }
        __syncthreads();
    }

    // epilogue
    float*  C32 = (float*)Cv;
    __half* C16 = (__half*)Cv;
#pragma unroll
    for (int im = 0; im < 2; im++) {
#pragma unroll
        for (int nt = 0; nt < 8; nt++) {
            int row0 = rowBase + mb + im * 16 + g;
            int col  = colBase + nb + nt * 8 + tg * 2;
            float bx = 0.f, by = 0.f;
            if (bias) { bx = bias[col]; by = bias[col + 1]; }
#pragma unroll
            for (int h = 0; h < 2; h++) {
                int row = row0 + h * 8;
                if (row < M) {
                    float ox = acc[im][nt][h * 2 + 0] + bx;
                    float oy = acc[im][nt][h * 2 + 1] + by;
                    if (OUT16) {
                        *(__half2*)&C16[(size_t)row * ncols + col] =
                            __floats2half2_rn(ox, oy);
                    } else {
                        *(float2*)&C32[(size_t)row * ncols + col] =
                            make_float2(ox, oy);
                    }
                }
            }
        }
    }
}

// ---------------- CSR aggregation + fused BN stats ----------------
// 64 threads per node (4 feats each), 4 nodes per 256-thread block.
// out[n] = dinv[n]^2 * h[n] + bias + sum_j coef_j * h[src_j]   (h in fp16)
// Also accumulates per-column sum / sumsq into g_stats.
__global__ void k_agg_csr(const __half* __restrict__ h, float* __restrict__ out,
                          const float* __restrict__ bias) {
    __shared__ float s_sum[4][256];
    __shared__ float s_sq [4][256];

    int grp  = threadIdx.x >> 6;
    int lane = threadIdx.x & 63;
    int node = blockIdx.x * 4 + grp;
    int f = lane * 4;

    float4 acc = make_float4(0.f, 0.f, 0.f, 0.f);
    if (node < NN) {
        float di = g_dinv[node];
        float cs = di * di;
        uint2 raw = *(const uint2*)&h[(size_t)node * 256 + f];
        float2 v01 = __half22float2(*(__half2*)&raw.x);
        float2 v23 = __half22float2(*(__half2*)&raw.y);
        float4 b = *(const float4*)&bias[f];
        acc.x = v01.x * cs + b.x;
        acc.y = v01.y * cs + b.y;
        acc.z = v23.x * cs + b.z;
        acc.w = v23.y * cs + b.w;

        int beg = g_ptr[node];
        int end = beg + g_cnt[node];
        if (beg < end) {
            int   s = g_csr_src[beg];
            float c = g_csr_coef[beg];
            for (int j = beg; j < end; j++) {
                uint2 r2 = *(const uint2*)&h[(size_t)s * 256 + f];
                int jn = j + 1;
                int s2 = 0; float c2 = 0.f;
                if (jn < end) { s2 = g_csr_src[jn]; c2 = g_csr_coef[jn]; }
                float2 w01 = __half22float2(*(__half2*)&r2.x);
                float2 w23 = __half22float2(*(__half2*)&r2.y);
                acc.x += c * w01.x; acc.y += c * w01.y;
                acc.z += c * w23.x; acc.w += c * w23.y;
                s = s2; c = c2;
            }
        }
        *(float4*)&out[(size_t)node * 256 + f] = acc;
    }

    // per-block BN partials
    s_sum[grp][f + 0] = acc.x; s_sum[grp][f + 1] = acc.y;
    s_sum[grp][f + 2] = acc.z; s_sum[grp][f + 3] = acc.w;
    s_sq [grp][f + 0] = acc.x * acc.x; s_sq[grp][f + 1] = acc.y * acc.y;
    s_sq [grp][f + 2] = acc.z * acc.z; s_sq[grp][f + 3] = acc.w * acc.w;
    __syncthreads();

    int t = threadIdx.x;   // 0..255 = feature
    float s = s_sum[0][t] + s_sum[1][t] + s_sum[2][t] + s_sum[3][t];
    float q = s_sq [0][t] + s_sq [1][t] + s_sq [2][t] + s_sq [3][t];
    atomicAdd(&g_stats[t], s);
    atomicAdd(&g_stats[HDIM + t], q);
}

// compute scale/shift, then zero stats for the next layer
__global__ void k_bn_final(const float* __restrict__ gamma, const float* __restrict__ beta) {
    int f = threadIdx.x;
    float inv_n = 1.0f / (float)NN;
    float m  = g_stats[f] * inv_n;
    float v  = g_stats[HDIM + f] * inv_n - m * m;
    float sc = gamma[f] * rsqrtf(v + BN_EPS);
    g_ss[f]        = sc;
    g_ss[HDIM + f] = beta[f] - m * sc;
    g_stats[f] = 0.0f;
    g_stats[HDIM + f] = 0.0f;
}

// ---------------- launch ----------------
extern "C" void kernel_launch(void* const* d_in, const int* in_sizes, int n_in,
                              void* d_out, int out_size) {
    const float* x   = (const float*)d_in[0];
    const int*   ei  = (const int*)  d_in[1];   // [2, E]: src then dst
    const float* W0  = (const float*)d_in[2];
    const float* b0  = (const float*)d_in[3];
    const float* g0  = (const float*)d_in[4];
    const float* be0 = (const float*)d_in[5];
    const float* W1  = (const float*)d_in[6];
    const float* b1  = (const float*)d_in[7];
    const float* g1  = (const float*)d_in[8];
    const float* be1 = (const float*)d_in[9];
    const float* Wmu = (const float*)d_in[10];
    const float* bmu = (const float*)d_in[11];
    const float* Wlv = (const float*)d_in[12];
    const float* blv = (const float*)d_in[13];
    float* out = (float*)d_out;

    const int* src = ei;
    const int* dst = ei + EE;

    float  *bufA = nullptr, *bufB = nullptr;
    __half *h16  = nullptr;
    cudaGetSymbolAddress((void**)&bufA, g_bufA);
    cudaGetSymbolAddress((void**)&bufB, g_bufB);
    cudaGetSymbolAddress((void**)&h16,  g_h16);

    const int NB_N  = (NN + 255) / 256;     // 196
    const int NB_E  = (EE + 255) / 256;
    const int NB_AG = (NN + 3) / 4;         // 12500
    const dim3 G_GEMM_H((NN + 127) / 128, 2);    // ncols=256
    const dim3 G_GEMM_L((NN + 127) / 128, 1);    // ncols=128

    // --- graph preprocessing ---
    k_cnt_zero<<<NB_N, 256>>>();
    k_cnt     <<<NB_E, 256>>>(dst);
    k_dinv    <<<NB_N, 256>>>();            // also zeroes g_stats
    k_bsum    <<<SCAN_B, 256>>>();
    k_bscan   <<<1, 256>>>();
    k_ptr     <<<SCAN_B, 256>>>();
    k_fill    <<<NB_E, 256>>>(src, dst);

    // --- layer 0: gemm (raw x) -> fp16 h; agg+stats; bn coeffs ---
    sgemm_tf32<false, true><<<G_GEMM_H, 256>>>(x, W0, nullptr, h16, NN, HDIM);
    k_agg_csr <<<NB_AG, 256>>>(h16, bufA, b0);
    k_bn_final<<<1, 256>>>(g0, be0);

    // --- layer 1: gemm (BN+ReLU fused on A) -> fp16 h; agg+stats; bn coeffs ---
    sgemm_tf32<true, true><<<G_GEMM_H, 256>>>(bufA, W1, nullptr, h16, NN, HDIM);
    k_agg_csr <<<NB_AG, 256>>>(h16, bufB, b1);
    k_bn_final<<<1, 256>>>(g1, be1);

    // --- heads: gemm (BN+ReLU fused on A), fp32 out; mu then logvar ---
    sgemm_tf32<true, false><<<G_GEMM_L, 256>>>(bufB, Wmu, bmu, out, NN, LDIM);
    sgemm_tf32<true, false><<<G_GEMM_L, 256>>>(bufB, Wlv, blv, out + (size_t)NN * LDIM, NN, LDIM);
}

// round 4
// speedup vs baseline: 2.4669x; 1.3616x over previous
#include <cuda_runtime.h>
#include <cuda_fp16.h>
#include <stdint.h>

#define NN   50000
#define EE   800000
#define HDIM 256
#define LDIM 128
#define BN_EPS 1e-5f
#define SCAN_B 196          // ceil(NN/256)
#define KP   264            // padded K stride (halves): 256+8 -> conflict-free ldmatrix

// ---------------- scratch (static device globals; no allocation) ----------------
__device__ float  g_dinv[NN];
__device__ int    g_cnt [NN];
__device__ int    g_ptr [NN];
__device__ int    g_pos [NN];
__device__ int    g_bsum[256];
__device__ int    g_boff[256];
__device__ int2   g_csr [EE];                    // x=src, y=coef bits
__device__ __half g_h16[(size_t)NN * HDIM];      // 25.6 MB (GEMM out, agg in)
__device__ float  g_bufA[(size_t)NN * HDIM];     // agg out layer 0
__device__ float  g_bufB[(size_t)NN * HDIM];     // agg out layer 1
__device__ float  g_stats[2 * HDIM];             // col sum / sumsq
__device__ float  g_ss   [2 * HDIM];             // scale / shift
__device__ __half g_w0t[HDIM * HDIM];            // W0^T  [n][k]
__device__ __half g_w1t[HDIM * HDIM];            // W1^T  [n][k]
__device__ __half g_wmt[LDIM * HDIM];            // Wmu^T [n][k]
__device__ __half g_wlt[LDIM * HDIM];            // Wlv^T [n][k]

// ---------------- helpers ----------------
__device__ __forceinline__ void mma_f16(float* c, const uint32_t* a,
                                        uint32_t b0, uint32_t b1) {
    asm volatile(
        "mma.sync.aligned.m16n8k16.row.col.f32.f16.f16.f32 "
        "{%0,%1,%2,%3}, {%4,%5,%6,%7}, {%8,%9}, {%0,%1,%2,%3};\n"
        : "+f"(c[0]), "+f"(c[1]), "+f"(c[2]), "+f"(c[3])
        : "r"(a[0]), "r"(a[1]), "r"(a[2]), "r"(a[3]), "r"(b0), "r"(b1));
}

// ---------------- graph preprocessing ----------------
__global__ void k_cnt_zero() {
    int i = blockIdx.x * blockDim.x + threadIdx.x;
    if (i < NN) g_cnt[i] = 0;
}

__global__ void k_cnt(const int* __restrict__ dst) {
    int e = blockIdx.x * blockDim.x + threadIdx.x;
    if (e < EE) atomicAdd(&g_cnt[dst[e]], 1);
}

// dinv + zero stats + transpose/convert all weights to fp16 [n][k]
__global__ void k_dinv_wcvt(const float* __restrict__ W0, const float* __restrict__ W1,
                            const float* __restrict__ Wmu, const float* __restrict__ Wlv) {
    int b = blockIdx.x;
    if (b < SCAN_B) {
        int i = b * 256 + threadIdx.x;
        if (i < NN) g_dinv[i] = rsqrtf((float)g_cnt[i] + 1.0f);
        if (b == 0 && threadIdx.x < 2 * HDIM) g_stats[threadIdx.x] = 0.0f;
        return;
    }
    int idx = (b - SCAN_B) * 256 + threadIdx.x;      // 0 .. 196607
    if (idx < 65536) {
        int n = idx >> 8, k = idx & 255;
        g_w0t[idx] = __float2half(W0[k * 256 + n]);
    } else if (idx < 131072) {
        int j = idx - 65536; int n = j >> 8, k = j & 255;
        g_w1t[j] = __float2half(W1[k * 256 + n]);
    } else if (idx < 163840) {
        int j = idx - 131072; int n = j >> 8, k = j & 255;
        g_wmt[j] = __float2half(Wmu[k * 128 + n]);
    } else if (idx < 196608) {
        int j = idx - 163840; int n = j >> 8, k = j & 255;
        g_wlt[j] = __float2half(Wlv[k * 128 + n]);
    }
}

__global__ void k_bsum() {
    __shared__ int sm[256];
    int t = threadIdx.x;
    int i = blockIdx.x * 256 + t;
    sm[t] = (i < NN) ? g_cnt[i] : 0;
    __syncthreads();
    for (int off = 128; off > 0; off >>= 1) {
        if (t < off) sm[t] += sm[t + off];
        __syncthreads();
    }
    if (t == 0) g_bsum[blockIdx.x] = sm[0];
}

__global__ void k_bscan() {
    __shared__ int sm[256];
    int t = threadIdx.x;
    int v = (t < SCAN_B) ? g_bsum[t] : 0;
    sm[t] = v;
    __syncthreads();
    for (int off = 1; off < 256; off <<= 1) {
        int u = (t >= off) ? sm[t - off] : 0;
        __syncthreads();
        sm[t] += u;
        __syncthreads();
    }
    g_boff[t] = sm[t] - v;
}

__global__ void k_ptr() {
    __shared__ int sm[256];
    int t = threadIdx.x;
    int i = blockIdx.x * 256 + t;
    int c = (i < NN) ? g_cnt[i] : 0;
    sm[t] = c;
    __syncthreads();
    for (int off = 1; off < 256; off <<= 1) {
        int u = (t >= off) ? sm[t - off] : 0;
        __syncthreads();
        sm[t] += u;
        __syncthreads();
    }
    if (i < NN) {
        int p = g_boff[blockIdx.x] + sm[t] - c;
        g_ptr[i] = p;
        g_pos[i] = p;
    }
}

__global__ void k_fill(const int* __restrict__ src, const int* __restrict__ dst) {
    int e = blockIdx.x * blockDim.x + threadIdx.x;
    if (e >= EE) return;
    int s = src[e], d = dst[e];
    int p = atomicAdd(&g_pos[d], 1);
    float c = g_dinv[s] * g_dinv[d];
    g_csr[p] = make_int2(s, __float_as_int(c));
}

// ---------------- fp16 tensor-core GEMM (full-K smem resident) ----------------
// C[M, ncols] = act(A)[M,256] @ Wt^T, Wt is fp16 [n][k].
// BM=64, BN=128, 128 threads = 4 warps (2m x 2n), warp tile 32x64.
// FUSE_BN: act(v)=relu(v*g_ss[k]+g_ss[256+k]) at A load. OUT16: fp16 output.
template <bool FUSE_BN, bool OUT16>
__global__ void gemm_f16(const float* __restrict__ A, const __half* __restrict__ Wt,
                         const float* __restrict__ bias, void* __restrict__ Cv,
                         int M, int ncols) {
    extern __shared__ __half smem[];
    __half* As = smem;              // 64 x KP
    __half* Bs = smem + 64 * KP;    // 128 x KP

    int tid  = threadIdx.x;
    int wid  = tid >> 5;
    int lane = tid & 31;
    int g    = lane >> 2;
    int tg   = lane & 3;
    int mb   = (wid & 1) * 32;
    int nb   = (wid >> 1) * 64;
    int rowBase = blockIdx.x * 64;
    int colBase = blockIdx.y * 128;

    // A: 64 rows x 256 fp32 -> fp16 smem (BN+ReLU fused). 4096 float4 / 128 thr.
#pragma unroll
    for (int i = 0; i < 32; i++) {
        int f4 = tid + i * 128;
        int r  = f4 >> 6;                // 64 float4 per row
        int c  = (f4 & 63) << 2;
        float4 v = make_float4(0.f, 0.f, 0.f, 0.f);
        int gr = rowBase + r;
        if (gr < M) v = *(const float4*)&A[(size_t)gr * 256 + c];
        if (FUSE_BN) {
            float4 sc = *(const float4*)&g_ss[c];
            float4 sh = *(const float4*)&g_ss[256 + c];
            v.x = fmaxf(v.x * sc.x + sh.x, 0.0f);
            v.y = fmaxf(v.y * sc.y + sh.y, 0.0f);
            v.z = fmaxf(v.z * sc.z + sh.z, 0.0f);
            v.w = fmaxf(v.w * sc.w + sh.w, 0.0f);
        }
        *(__half2*)&As[r * KP + c]     = __floats2half2_rn(v.x, v.y);
        *(__half2*)&As[r * KP + c + 2] = __floats2half2_rn(v.z, v.w);
    }
    // B: 128 rows x 256 halves, contiguous copy. 4096 uint4 slots? -> 8 halves each.
#pragma unroll
    for (int i = 0; i < 32; i++) {
        int s = tid + i * 128;
        int n = s >> 5;                  // 32 uint4 per row
        int k = (s & 31) << 3;
        uint4 v = *(const uint4*)&Wt[(size_t)(colBase + n) * 256 + k];
        *(uint4*)&Bs[n * KP + k] = v;
    }
    __syncthreads();

    float acc[2][8][4] = {};
    uint32_t As_base = (uint32_t)__cvta_generic_to_shared(As);

#pragma unroll
    for (int kk = 0; kk < 256; kk += 16) {
        uint32_t a[2][4];
#pragma unroll
        for (int im = 0; im < 2; im++) {
            int row = mb + im * 16 + (lane & 15);
            int col = kk + ((lane >> 4) << 3);
            uint32_t addr = As_base + (uint32_t)(row * KP + col) * 2u;
            asm volatile(
                "ldmatrix.sync.aligned.m8n8.x4.shared.b16 {%0,%1,%2,%3}, [%4];"
                : "=r"(a[im][0]), "=r"(a[im][1]), "=r"(a[im][2]), "=r"(a[im][3])
                : "r"(addr));
        }
#pragma unroll
        for (int nt = 0; nt < 8; nt++) {
            const __half* bp = &Bs[(nb + nt * 8 + g) * KP + kk + 2 * tg];
            uint32_t b0 = *(const uint32_t*)bp;
            uint32_t b1 = *(const uint32_t*)(bp + 8);
            mma_f16(acc[0][nt], a[0], b0, b1);
            mma_f16(acc[1][nt], a[1], b0, b1);
        }
    }

    // epilogue
    float*  C32 = (float*)Cv;
    __half* C16 = (__half*)Cv;
#pragma unroll
    for (int im = 0; im < 2; im++) {
#pragma unroll
        for (int nt = 0; nt < 8; nt++) {
            int row0 = rowBase + mb + im * 16 + g;
            int col  = colBase + nb + nt * 8 + tg * 2;
            float bx = 0.f, by = 0.f;
            if (bias) { bx = bias[col]; by = bias[col + 1]; }
#pragma unroll
            for (int h = 0; h < 2; h++) {
                int row = row0 + h * 8;
                if (row < M) {
                    float ox = acc[im][nt][h * 2 + 0] + bx;
                    float oy = acc[im][nt][h * 2 + 1] + by;
                    if (OUT16) {
                        *(__half2*)&C16[(size_t)row * ncols + col] =
                            __floats2half2_rn(ox, oy);
                    } else {
                        *(float2*)&C32[(size_t)row * ncols + col] =
                            make_float2(ox, oy);
                    }
                }
            }
        }
    }
}

// ---------------- CSR aggregation + fused BN stats ----------------
__global__ void k_agg_csr(const __half* __restrict__ h, float* __restrict__ out,
                          const float* __restrict__ bias) {
    __shared__ float s_sum[4][256];
    __shared__ float s_sq [4][256];

    int grp  = threadIdx.x >> 6;
    int lane = threadIdx.x & 63;
    int node = blockIdx.x * 4 + grp;
    int f = lane * 4;

    float4 acc = make_float4(0.f, 0.f, 0.f, 0.f);
    if (node < NN) {
        float di = g_dinv[node];
        float cs = di * di;
        uint2 raw = *(const uint2*)&h[(size_t)node * 256 + f];
        float2 v01 = __half22float2(*(__half2*)&raw.x);
        float2 v23 = __half22float2(*(__half2*)&raw.y);
        float4 b = *(const float4*)&bias[f];
        acc.x = v01.x * cs + b.x;
        acc.y = v01.y * cs + b.y;
        acc.z = v23.x * cs + b.z;
        acc.w = v23.y * cs + b.w;

        int beg = g_ptr[node];
        int end = beg + g_cnt[node];
        if (beg < end) {
            int2 rec = g_csr[beg];
            for (int j = beg; j < end; j++) {
                int   s = rec.x;
                float c = __int_as_float(rec.y);
                uint2 r2 = *(const uint2*)&h[(size_t)s * 256 + f];
                if (j + 1 < end) rec = g_csr[j + 1];
                float2 w01 = __half22float2(*(__half2*)&r2.x);
                float2 w23 = __half22float2(*(__half2*)&r2.y);
                acc.x += c * w01.x; acc.y += c * w01.y;
                acc.z += c * w23.x; acc.w += c * w23.y;
            }
        }
        *(float4*)&out[(size_t)node * 256 + f] = acc;
    }

    s_sum[grp][f + 0] = acc.x; s_sum[grp][f + 1] = acc.y;
    s_sum[grp][f + 2] = acc.z; s_sum[grp][f + 3] = acc.w;
    s_sq [grp][f + 0] = acc.x * acc.x; s_sq[grp][f + 1] = acc.y * acc.y;
    s_sq [grp][f + 2] = acc.z * acc.z; s_sq[grp][f + 3] = acc.w * acc.w;
    __syncthreads();

    int t = threadIdx.x;
    float s = s_sum[0][t] + s_sum[1][t] + s_sum[2][t] + s_sum[3][t];
    float q = s_sq [0][t] + s_sq [1][t] + s_sq [2][t] + s_sq [3][t];
    atomicAdd(&g_stats[t], s);
    atomicAdd(&g_stats[HDIM + t], q);
}

__global__ void k_bn_final(const float* __restrict__ gamma, const float* __restrict__ beta) {
    int f = threadIdx.x;
    float inv_n = 1.0f / (float)NN;
    float m  = g_stats[f] * inv_n;
    float v  = g_stats[HDIM + f] * inv_n - m * m;
    float sc = gamma[f] * rsqrtf(v + BN_EPS);
    g_ss[f]        = sc;
    g_ss[HDIM + f] = beta[f] - m * sc;
    g_stats[f] = 0.0f;
    g_stats[HDIM + f] = 0.0f;
}

// ---------------- launch ----------------
extern "C" void kernel_launch(void* const* d_in, const int* in_sizes, int n_in,
                              void* d_out, int out_size) {
    const float* x   = (const float*)d_in[0];
    const int*   ei  = (const int*)  d_in[1];   // [2, E]: src then dst
    const float* W0  = (const float*)d_in[2];
    const float* b0  = (const float*)d_in[3];
    const float* g0  = (const float*)d_in[4];
    const float* be0 = (const float*)d_in[5];
    const float* W1  = (const float*)d_in[6];
    const float* b1  = (const float*)d_in[7];
    const float* g1  = (const float*)d_in[8];
    const float* be1 = (const float*)d_in[9];
    const float* Wmu = (const float*)d_in[10];
    const float* bmu = (const float*)d_in[11];
    const float* Wlv = (const float*)d_in[12];
    const float* blv = (const float*)d_in[13];
    float* out = (float*)d_out;

    const int* src = ei;
    const int* dst = ei + EE;

    float  *bufA = nullptr, *bufB = nullptr;
    __half *h16 = nullptr, *w0t = nullptr, *w1t = nullptr, *wmt = nullptr, *wlt = nullptr;
    cudaGetSymbolAddress((void**)&bufA, g_bufA);
    cudaGetSymbolAddress((void**)&bufB, g_bufB);
    cudaGetSymbolAddress((void**)&h16,  g_h16);
    cudaGetSymbolAddress((void**)&w0t,  g_w0t);
    cudaGetSymbolAddress((void**)&w1t,  g_w1t);
    cudaGetSymbolAddress((void**)&wmt,  g_wmt);
    cudaGetSymbolAddress((void**)&wlt,  g_wlt);

    const int NB_N  = SCAN_B;               // 196
    const int NB_E  = (EE + 255) / 256;
    const int NB_AG = (NN + 3) / 4;
    const int NB_DW = SCAN_B + 768;         // dinv blocks + weight-cvt blocks
    const dim3 G_H((NN + 63) / 64, 2);      // ncols=256
    const dim3 G_L((NN + 63) / 64, 1);      // ncols=128

    const int SMEM = (64 + 128) * KP * 2;   // 101376 bytes
    cudaFuncSetAttribute(gemm_f16<false, true>,
                         cudaFuncAttributeMaxDynamicSharedMemorySize, SMEM);
    cudaFuncSetAttribute(gemm_f16<true, true>,
                         cudaFuncAttributeMaxDynamicSharedMemorySize, SMEM);
    cudaFuncSetAttribute(gemm_f16<true, false>,
                         cudaFuncAttributeMaxDynamicSharedMemorySize, SMEM);

    // 1-3: counts, dinv + weight transpose (layer-0 GEMM deps only)
    k_cnt_zero  <<<NB_N, 256>>>();
    k_cnt       <<<NB_E, 256>>>(dst);
    k_dinv_wcvt <<<NB_DW, 256>>>(W0, W1, Wmu, Wlv);

    // 4: layer-0 hidden GEMM (the profiled launch)
    gemm_f16<false, true><<<G_H, 128, SMEM>>>(x, w0t, nullptr, h16, NN, HDIM);

    // 5-8: CSR build
    k_bsum <<<SCAN_B, 256>>>();
    k_bscan<<<1, 256>>>();
    k_ptr  <<<SCAN_B, 256>>>();
    k_fill <<<NB_E, 256>>>(src, dst);

    // layer 0 aggregation + BN coeffs
    k_agg_csr <<<NB_AG, 256>>>(h16, bufA, b0);
    k_bn_final<<<1, 256>>>(g0, be0);

    // layer 1
    gemm_f16<true, true><<<G_H, 128, SMEM>>>(bufA, w1t, nullptr, h16, NN, HDIM);
    k_agg_csr <<<NB_AG, 256>>>(h16, bufB, b1);
    k_bn_final<<<1, 256>>>(g1, be1);

    // heads: mu then logvar
    gemm_f16<true, false><<<G_L, 128, SMEM>>>(bufB, wmt, bmu, out, NN, LDIM);
    gemm_f16<true, false><<<G_L, 128, SMEM>>>(bufB, wlt, blv, out + (size_t)NN * LDIM, NN, LDIM);
}